// round 13
// baseline (speedup 1.0000x reference)
#include <cuda_runtime.h>
#include <cstddef>

#define IMH 1024
#define IMW 1024
#define SFRAMES 8
#define NB 4
#define TR 32            // tile rows (output)
#define TC 64            // tile cols
#define NTHREADS 256
#define NW 8             // warps
#define GH (TR + 8)      // 40 rows incl vertical halo

// smem: interleaved (hA, hB) float2 per pixel, GH x TC
#define SMEM_FLOATS (GH * TC * 2)
#define SMEM_BYTES  (SMEM_FLOATS * 4)      // 20,480 B

__device__ __forceinline__ int reflect101(int i, int n) {
    if (i < 0) i = -i;
    if (i >= n) i = 2 * n - 2 - i;
    return i;
}

// ============================================================================
// Fused: 8-frame laplacian-of-gaussian + argmax + L1-hot winner RGB tracking
//  P1+P2 fused via warp shuffle (no gray smem); P3: 8-row x 1-col streaming.
// ============================================================================
extern "C" __global__ void __launch_bounds__(NTHREADS, 4)
lap_merge_kernel(const float* __restrict__ x, float* __restrict__ out)
{
    extern __shared__ float smem[];
    float* sHAB = smem;                    // (r*TC + c)*2 -> {hA, hB}

    const int tid  = threadIdx.x;
    const int lane = tid & 31;
    const int warp = tid >> 5;
    const int b    = blockIdx.z;
    const int hr0  = blockIdx.y * TR;
    const int wc0  = blockIdx.x * TC;
    const size_t HW = (size_t)IMH * IMW;
    const float ONE3 = 0.33333334f;
    const bool interior = (blockIdx.x != 0) && ((int)blockIdx.x != (int)gridDim.x - 1);

    // per-thread state: 8 px = 8 rows x 1 col
    const int r0  = (tid >> 6) * 8;         // 4 row-groups x 8 rows = 32 rows
    const int col = tid & 63;               // 64 cols

    float bestLap[8], bR[8], bG[8], bB[8];
#pragma unroll
    for (int rr = 0; rr < 8; rr++) bestLap[rr] = -3.0e38f;

    for (int s = 0; s < SFRAMES; s++) {
        const float* __restrict__ xf = x + ((size_t)(b * SFRAMES + s)) * 3 * HW;

        // ==== P1+P2 fused: gray in regs -> shuffle window -> hconv -> sHAB ====
        for (int r = warp; r < GH; r += NW) {
            const int gr = reflect101(hr0 - 4 + r, IMH);
            const float* __restrict__ p0 = xf + (size_t)gr * IMW;

            float4 g4 = make_float4(0.f, 0.f, 0.f, 0.f);
            if (interior) {
                if (lane < 18) {
                    const float* __restrict__ p = p0 + (wc0 - 4 + lane * 4);
                    float4 a  = *reinterpret_cast<const float4*>(p);
                    float4 bq = *reinterpret_cast<const float4*>(p + HW);
                    float4 c  = *reinterpret_cast<const float4*>(p + 2 * HW);
                    g4.x = (a.x + bq.x + c.x) * ONE3;
                    g4.y = (a.y + bq.y + c.y) * ONE3;
                    g4.z = (a.z + bq.z + c.z) * ONE3;
                    g4.w = (a.w + bq.w + c.w) * ONE3;
                }
            } else {
                if (lane < 18) {
#pragma unroll
                    for (int k = 0; k < 4; k++) {
                        const int gc = reflect101(wc0 - 4 + lane * 4 + k, IMW);
                        (&g4.x)[k] = (__ldg(p0 + gc) + __ldg(p0 + gc + HW)
                                      + __ldg(p0 + gc + 2 * HW)) * ONE3;
                    }
                }
            }

            // window via register exchange (all lanes participate)
            float4 b1, c2;
            b1.x = __shfl_down_sync(0xFFFFFFFFu, g4.x, 1);
            b1.y = __shfl_down_sync(0xFFFFFFFFu, g4.y, 1);
            b1.z = __shfl_down_sync(0xFFFFFFFFu, g4.z, 1);
            b1.w = __shfl_down_sync(0xFFFFFFFFu, g4.w, 1);
            c2.x = __shfl_down_sync(0xFFFFFFFFu, g4.x, 2);
            c2.y = __shfl_down_sync(0xFFFFFFFFu, g4.y, 2);
            c2.z = __shfl_down_sync(0xFFFFFFFFu, g4.z, 2);
            c2.w = __shfl_down_sync(0xFFFFFFFFu, g4.w, 2);

            if (lane < 16) {
                float w[12];
                w[0] = g4.x; w[1] = g4.y; w[2]  = g4.z; w[3]  = g4.w;
                w[4] = b1.x; w[5] = b1.y; w[6]  = b1.z; w[7]  = b1.w;
                w[8] = c2.x; w[9] = c2.y; w[10] = c2.z; w[11] = c2.w;
                float4 hA4, hB4;
#pragma unroll
                for (int o = 0; o < 4; o++) {
                    float p1 = w[o + 3] + w[o + 5];
                    float p2 = w[o + 2] + w[o + 6];
                    float p3 = w[o + 1] + w[o + 7];
                    float p4 = w[o + 0] + w[o + 8];
                    float ctr = w[o + 4];
                    (&hA4.x)[o] =  4.375f * ctr + 3.5f  * p1 + 1.75f * p2 + 0.5f  * p3 + 0.0625f * p4;
                    (&hB4.x)[o] = -0.625f * ctr - 0.25f * p1 + 0.25f * p2 + 0.25f * p3 + 0.0625f * p4;
                }
                float* dst = &sHAB[(r * TC + lane * 4) * 2];
                *reinterpret_cast<float4*>(dst)     = make_float4(hA4.x, hB4.x, hA4.y, hB4.y);
                *reinterpret_cast<float4*>(dst + 4) = make_float4(hA4.z, hB4.z, hA4.w, hB4.w);
            }
        }
        __syncthreads();

        // ==== P3: vertical 9-tap (B on hA + A on hB), 16-row stream + argmax ====
        {
            const float wAv[9] = {0.0625f, 0.5f, 1.75f, 3.5f, 4.375f, 3.5f, 1.75f, 0.5f, 0.0625f};
            const float wBv[9] = {0.0625f, 0.25f, 0.25f, -0.25f, -0.625f, -0.25f, 0.25f, 0.25f, 0.0625f};
            float acc[8];
#pragma unroll
            for (int rr = 0; rr < 8; rr++) acc[rr] = 0.f;

#pragma unroll
            for (int j = 0; j < 16; j++) {
                const float2 v = *reinterpret_cast<const float2*>(
                    &sHAB[((r0 + j) * TC + col) * 2]);
#pragma unroll
                for (int rr = 0; rr < 8; rr++) {
                    const int jj = j - rr;
                    if (jj >= 0 && jj <= 8) {    // static after unroll
                        acc[rr] += wBv[jj] * v.x + wAv[jj] * v.y;
                    }
                }
            }
#pragma unroll
            for (int rr = 0; rr < 8; rr++) {
                if (acc[rr] > bestLap[rr]) {     // strict > == first-max (jnp.argmax)
                    bestLap[rr] = acc[rr];
                    // winner RGB reload: bytes just read by P1 -> L1 hit
                    const float* __restrict__ xw =
                        xf + (size_t)(hr0 + r0 + rr) * IMW + (wc0 + col);
                    bR[rr] = __ldg(xw);
                    bG[rr] = __ldg(xw + HW);
                    bB[rr] = __ldg(xw + 2 * HW);
                }
            }
        }
        __syncthreads();   // sHAB reused by next frame
    }

    // ==== Epilogue: write winner RGB (b, c, h, w) ====
#pragma unroll
    for (int rr = 0; rr < 8; rr++) {
        const size_t obase = ((size_t)(b * 3) * IMH + (hr0 + r0 + rr)) * IMW + wc0 + col;
        out[obase]          = bR[rr];
        out[obase + HW]     = bG[rr];
        out[obase + 2 * HW] = bB[rr];
    }
}

// ============================================================================
extern "C" void kernel_launch(void* const* d_in, const int* in_sizes, int n_in,
                              void* d_out, int out_size)
{
    const float* x = (const float*)d_in[0];
    float* out = (float*)d_out;

    cudaFuncSetAttribute(lap_merge_kernel,
                         cudaFuncAttributeMaxDynamicSharedMemorySize, SMEM_BYTES);

    dim3 grid(IMW / TC, IMH / TR, NB);
    lap_merge_kernel<<<grid, NTHREADS, SMEM_BYTES>>>(x, out);
}